// round 11
// baseline (speedup 1.0000x reference)
#include <cuda_runtime.h>
#include <cuda_fp16.h>
#include <math.h>

static constexpr int N_NODES = 100000;
static constexpr int N_EDGES = 1600000;
static constexpr int D = 128;

// ---------------- scratch (device globals; no runtime allocation) ----------------
__device__ __align__(16) __half g_nft[N_NODES * D];       // fp16: A@W2^T + b2
__device__ __align__(16) __half g_gih[N_NODES * 384];     // fp16 gate pre-activations
__device__ __align__(16) __half g_ghh[N_NODES * 384];
__device__ __align__(16) __half g_ah[N_NODES * D];        // A in fp16 (RN)
__device__ __align__(16) __half g_oh[N_NODES * D];        // out_emb in fp16 (RN)
__device__ __align__(16) __half g_w2[128 * D];            // weights fp16
__device__ __align__(16) __half g_wih[384 * D];
__device__ __align__(16) __half g_whh[384 * D];
__device__ float g_logit[N_NODES];
__device__ float g_logit_src[N_NODES];
__device__ int   g_cnt[N_NODES];
__device__ int   g_start[N_NODES];
__device__ int   g_cursor[N_NODES];
__device__ __align__(8) int2 g_pack[N_EDGES];             // {src, bits(exp(score))}
__device__ int   g_counter;
__device__ int   g_is64;

// ---------------- fp16 helpers ----------------
__device__ __forceinline__ void cvt4_h(float4 v, __half* dst, long long i4) {
    __half2 p0 = __floats2half2_rn(v.x, v.y);
    __half2 p1 = __floats2half2_rn(v.z, v.w);
    uint2 u;
    u.x = *reinterpret_cast<unsigned*>(&p0);
    u.y = *reinterpret_cast<unsigned*>(&p1);
    reinterpret_cast<uint2*>(dst)[i4] = u;
}
__device__ __forceinline__ float4 h4_to_f4(uint2 u) {
    __half2 a = *reinterpret_cast<__half2*>(&u.x);
    __half2 b = *reinterpret_cast<__half2*>(&u.y);
    float2 fa = __half22float2(a), fb = __half22float2(b);
    return make_float4(fa.x, fa.y, fb.x, fb.y);
}

// dtype-adaptive edge index load, clamped to [0, N_NODES).
__device__ __forceinline__ int load_idx(const void* ei, long long i, int is64) {
    long long v = is64 ? reinterpret_cast<const long long*>(ei)[i]
                       : (long long)reinterpret_cast<const int*>(ei)[i];
    v = v < 0 ? 0 : (v >= N_NODES ? N_NODES - 1 : v);
    return (int)v;
}

// ---------------- small kernels ----------------
__global__ void k_zero(const int* __restrict__ eiw) {
    int i = blockIdx.x * blockDim.x + threadIdx.x;
    if (i < N_NODES) g_cnt[i] = 0;
    if (i == 0) {
        g_counter = 0;
        g_is64 = (eiw[1] == 0 && eiw[3] == 0 && eiw[5] == 0 && eiw[7] == 0) ? 1 : 0;
    }
}

__global__ void k_cvtW(const float* __restrict__ W2, const float* __restrict__ wih,
                       const float* __restrict__ whh) {
    int i = blockIdx.x * blockDim.x + threadIdx.x;
    const int n2 = 128 * 32, nih = 384 * 32;
    if (i < n2)
        cvt4_h(reinterpret_cast<const float4*>(W2)[i], g_w2, i);
    else if (i < n2 + nih)
        cvt4_h(reinterpret_cast<const float4*>(wih)[i - n2], g_wih, i - n2);
    else if (i < n2 + 2 * nih)
        cvt4_h(reinterpret_cast<const float4*>(whh)[i - n2 - nih], g_whh, i - n2 - nih);
}

// merged: per-node logits AND fp16 conversion of A (single pass over A)
__global__ void k_logits(const float* __restrict__ A, const float* __restrict__ W1) {
    int gid = blockIdx.x * blockDim.x + threadIdx.x;
    int node = gid >> 5, lane = gid & 31;
    if (node >= N_NODES) return;
    float4 x  = reinterpret_cast<const float4*>(A)[node * 32 + lane];
    cvt4_h(x, g_ah, (long long)node * 32 + lane);
    float4 wd = __ldg(reinterpret_cast<const float4*>(W1) + lane);
    float4 ws = __ldg(reinterpret_cast<const float4*>(W1) + 32 + lane);
    float d = x.x * wd.x + x.y * wd.y + x.z * wd.z + x.w * wd.w;
    float s = x.x * ws.x + x.y * ws.y + x.z * ws.z + x.w * ws.w;
#pragma unroll
    for (int o = 16; o; o >>= 1) {
        d += __shfl_xor_sync(0xffffffffu, d, o);
        s += __shfl_xor_sync(0xffffffffu, s, o);
    }
    if (lane == 0) { g_logit[node] = d; g_logit_src[node] = s; }
}

__global__ void k_count(const void* __restrict__ ei) {
    int e = blockIdx.x * blockDim.x + threadIdx.x;
    if (e >= N_EDGES) return;
    atomicAdd(&g_cnt[load_idx(ei, (long long)N_EDGES + e, g_is64)], 1);
}

__global__ void k_alloc() {
    int n = blockIdx.x * blockDim.x + threadIdx.x;
    if (n >= N_NODES) return;
    int c = g_cnt[n];
    int s = atomicAdd(&g_counter, c);
    g_start[n] = s;
    g_cursor[n] = s;
}

// segment_max elided: cancels exactly in attn = e/denom; scores are O(1).
__global__ void k_fill(const void* __restrict__ ei, const float* __restrict__ b1) {
    int e = blockIdx.x * blockDim.x + threadIdx.x;
    if (e >= N_EDGES) return;
    int is64 = g_is64;
    int src = load_idx(ei, e, is64);
    int dst = load_idx(ei, (long long)N_EDGES + e, is64);
    float sc = g_logit[dst] + g_logit_src[src] + __ldg(b1);
    sc = sc > 0.f ? sc : 0.2f * sc;
    float es = expf(sc);
    int pos = atomicAdd(&g_cursor[dst], 1);
    if (pos < N_EDGES) g_pack[pos] = make_int2(src, __float_as_int(es));
}

// warp per node: denom + weighted gather (fp16 nft) + ELU + deg select; writes fp16 oemb
__global__ void k_agg(const float* __restrict__ A) {
    int gid = blockIdx.x * blockDim.x + threadIdx.x;
    int node = gid >> 5, lane = gid & 31;
    if (node >= N_NODES) return;
    int s0 = g_start[node];
    int len = g_cnt[node];
    if (s0 + len > N_EDGES) len = N_EDGES - s0 > 0 ? N_EDGES - s0 : 0;

    float dsum = 0.f;
    for (int t = lane; t < len; t += 32) dsum += __int_as_float(g_pack[s0 + t].y);
#pragma unroll
    for (int o = 16; o; o >>= 1) dsum += __shfl_xor_sync(0xffffffffu, dsum, o);

    float4 out;
    if (len > 0) {
        float inv = 1.f / dsum;
        float ax = 0.f, ay = 0.f, az = 0.f, aw = 0.f;
        const uint2* nf = reinterpret_cast<const uint2*>(g_nft);
#pragma unroll 2
        for (int t = 0; t < len; ++t) {
            int2 p = g_pack[s0 + t];
            float w = __int_as_float(p.y) * inv;
            float4 v = h4_to_f4(nf[(size_t)p.x * 32 + lane]);
            ax = fmaf(w, v.x, ax); ay = fmaf(w, v.y, ay);
            az = fmaf(w, v.z, az); aw = fmaf(w, v.w, aw);
        }
        out.x = ax > 0.f ? ax : (expf(ax) - 1.f);
        out.y = ay > 0.f ? ay : (expf(ay) - 1.f);
        out.z = az > 0.f ? az : (expf(az) - 1.f);
        out.w = aw > 0.f ? aw : (expf(aw) - 1.f);
    } else {
        out = reinterpret_cast<const float4*>(A)[node * 32 + lane];
    }
    cvt4_h(out, g_oh, (long long)node * 32 + lane);
}

// ---------------- HMMA GEMM: persistent-column, double-buffered W ----
// One CTA per 128-row slab. X tile loaded ONCE; loop over column tiles,
// W tiles double-buffered via cp.async. Group discipline: commit {X,W0},{W1},
// then one commit per iteration (W_{j+2} or empty) -> uniform wait_group 1.
// smem row = 256B (16 chunks of 16B), phys chunk = ch ^ (row&7).

static constexpr int SM_X  = 0;
static constexpr int SM_W0 = 32768;
static constexpr int SM_W1 = 65536;
static constexpr int SM_TOTAL = 98304;

__device__ __forceinline__ unsigned smem_u32(const void* p) {
    unsigned a;
    asm("{ .reg .u64 t; cvta.to.shared.u64 t, %1; cvt.u32.u64 %0, t; }" : "=r"(a) : "l"(p));
    return a;
}
__device__ __forceinline__ void cpasync16(unsigned dst, const void* src, bool valid) {
    int sz = valid ? 16 : 0;
    asm volatile("cp.async.cg.shared.global [%0], [%1], 16, %2;"
                 :: "r"(dst), "l"(src), "r"(sz) : "memory");
}
__device__ __forceinline__ void ldsm4(unsigned& r0, unsigned& r1, unsigned& r2, unsigned& r3, unsigned a) {
    asm volatile("ldmatrix.sync.aligned.m8n8.x4.shared.b16 {%0,%1,%2,%3}, [%4];"
                 : "=r"(r0), "=r"(r1), "=r"(r2), "=r"(r3) : "r"(a));
}
__device__ __forceinline__ void mma16816(float* c, unsigned a0, unsigned a1, unsigned a2, unsigned a3,
                                         unsigned b0, unsigned b1) {
    asm volatile("mma.sync.aligned.m16n8k16.row.col.f32.f16.f16.f32 "
                 "{%0,%1,%2,%3}, {%4,%5,%6,%7}, {%8,%9}, {%0,%1,%2,%3};"
                 : "+f"(c[0]), "+f"(c[1]), "+f"(c[2]), "+f"(c[3])
                 : "r"(a0), "r"(a1), "r"(a2), "r"(a3), "r"(b0), "r"(b1));
}

// per-column-tile parameters
__device__ __forceinline__ void tile_params(
    int mode, int j, const __half*& W, int& wbase, __half*& C, int& mc, int& cb,
    const float*& bias, const float* b2, const float* bih, const float* bhh)
{
    if (mode == 0) {
        if (j == 0) { W = g_w2;  wbase = 0;            C = g_nft; mc = 128; cb = 0;            bias = b2;  }
        else        { W = g_whh; wbase = (j - 1) * 128; C = g_ghh; mc = 384; cb = (j - 1) * 128; bias = bhh; }
    } else          { W = g_wih; wbase = j * 128;       C = g_gih; mc = 384; cb = j * 128;       bias = bih; }
}

__global__ __launch_bounds__(256, 2) void k_hmma(
    int mode,                     // 0 = nft+gh (T=4), 1 = gi (T=3); grid = RT x 1
    const float* __restrict__ b2,
    const float* __restrict__ bih,
    const float* __restrict__ bhh)
{
    extern __shared__ __align__(128) char smem[];
    const int tid = threadIdx.x, wid = tid >> 5, lane = tid & 31;
    const unsigned sb = smem_u32(smem);
    const int rowBase = blockIdx.x * 128;
    const int T = (mode == 0) ? 4 : 3;
    const __half* Xp = (mode == 0) ? g_ah : g_oh;

    // ---- initial loads: group0 = {X, W0}, group1 = {W1} ----
    {
        const __half* W0; int wb0, mc, cb; __half* C; const float* bs;
        tile_params(mode, 0, W0, wb0, C, mc, cb, bs, b2, bih, bhh);
#pragma unroll
        for (int it = 0; it < 8; ++it) {
            int lc  = it * 256 + tid;
            int row = lc >> 4;
            int ch  = lc & 15;
            unsigned so = (unsigned)(row * 256 + ((ch ^ (row & 7)) << 4));
            int gr = rowBase + row;
            cpasync16(sb + SM_X + so, Xp + (size_t)gr * 128 + ch * 8, gr < N_NODES);
            cpasync16(sb + SM_W0 + so, W0 + (size_t)(wb0 + row) * 128 + ch * 8, true);
        }
        asm volatile("cp.async.commit_group;" ::: "memory");
        const __half* W1; int wb1;
        tile_params(mode, 1, W1, wb1, C, mc, cb, bs, b2, bih, bhh);
#pragma unroll
        for (int it = 0; it < 8; ++it) {
            int lc  = it * 256 + tid;
            int row = lc >> 4;
            int ch  = lc & 15;
            unsigned so = (unsigned)(row * 256 + ((ch ^ (row & 7)) << 4));
            cpasync16(sb + SM_W1 + so, W1 + (size_t)(wb1 + row) * 128 + ch * 8, true);
        }
        asm volatile("cp.async.commit_group;" ::: "memory");
    }

    const int warpRow = (wid >> 2) * 64;   // 0 or 64
    const int warpCol = (wid & 3) * 32;    // 0,32,64,96
    const int arow = warpRow + (lane & 15);
    const int ahalf = lane >> 4;
    const int bn0 = warpCol + ((lane >> 4) << 3) + (lane & 7);
    const int bhalf = (lane >> 3) & 1;
    const unsigned ab = sb + SM_X;

    for (int j = 0; j < T; ++j) {
        // need groups 0..j complete; exactly one prefetch may remain in flight
        asm volatile("cp.async.wait_group 1;" ::: "memory");
        __syncthreads();

        const __half* Wj; int wbj, mCols, colBase; __half* C; const float* bias;
        tile_params(mode, j, Wj, wbj, C, mCols, colBase, bias, b2, bih, bhh);
        const unsigned bb = sb + ((j & 1) ? SM_W1 : SM_W0);

        float acc[4][4][4];
#pragma unroll
        for (int mi = 0; mi < 4; ++mi)
#pragma unroll
            for (int nj = 0; nj < 4; ++nj)
#pragma unroll
                for (int q = 0; q < 4; ++q) acc[mi][nj][q] = 0.f;

#pragma unroll
        for (int s = 0; s < 8; ++s) {
            unsigned a[4][4];
#pragma unroll
            for (int mi = 0; mi < 4; ++mi) {
                int r = arow + mi * 16;
                unsigned ch = (unsigned)((2 * s + ahalf) ^ (r & 7));
                ldsm4(a[mi][0], a[mi][1], a[mi][2], a[mi][3], ab + r * 256 + (ch << 4));
            }
            unsigned b[2][4];
#pragma unroll
            for (int q = 0; q < 2; ++q) {
                int n = bn0 + q * 16;
                unsigned ch = (unsigned)((2 * s + bhalf) ^ (n & 7));
                ldsm4(b[q][0], b[q][1], b[q][2], b[q][3], bb + n * 256 + (ch << 4));
            }
#pragma unroll
            for (int mi = 0; mi < 4; ++mi) {
#pragma unroll
                for (int nj = 0; nj < 4; ++nj) {
                    unsigned b0 = b[nj >> 1][(nj & 1) * 2];
                    unsigned b1 = b[nj >> 1][(nj & 1) * 2 + 1];
                    mma16816(acc[mi][nj], a[mi][0], a[mi][1], a[mi][2], a[mi][3], b0, b1);
                }
            }
        }

        // all warps done reading this W buffer before it is overwritten
        __syncthreads();

        // prefetch W(j+2) into the buffer just freed; ALWAYS commit one group
        if (j + 2 < T) {
            const __half* Wn; int wbn, mc2, cb2; __half* C2; const float* bs2;
            tile_params(mode, j + 2, Wn, wbn, C2, mc2, cb2, bs2, b2, bih, bhh);
            unsigned dstb = sb + ((j & 1) ? SM_W1 : SM_W0);
#pragma unroll
            for (int it = 0; it < 8; ++it) {
                int lc  = it * 256 + tid;
                int row = lc >> 4;
                int ch  = lc & 15;
                unsigned so = (unsigned)(row * 256 + ((ch ^ (row & 7)) << 4));
                cpasync16(dstb + so, Wn + (size_t)(wbn + row) * 128 + ch * 8, true);
            }
        }
        asm volatile("cp.async.commit_group;" ::: "memory");

        // ---- epilogue: bias + fp16 store (overlaps the prefetch DMA) ----
        const int colOff = colBase + warpCol + 2 * (lane & 3);
#pragma unroll
        for (int nj = 0; nj < 4; ++nj) {
            int c = colOff + nj * 8;
            float2 b2v = __ldg(reinterpret_cast<const float2*>(bias + c));
#pragma unroll
            for (int mi = 0; mi < 4; ++mi) {
                int r0 = rowBase + warpRow + mi * 16 + (lane >> 2);
                if (r0 < N_NODES) {
                    __half2 h = __floats2half2_rn(acc[mi][nj][0] + b2v.x, acc[mi][nj][1] + b2v.y);
                    *reinterpret_cast<unsigned*>(C + (size_t)r0 * mCols + c) = *reinterpret_cast<unsigned*>(&h);
                }
                int r1 = r0 + 8;
                if (r1 < N_NODES) {
                    __half2 h = __floats2half2_rn(acc[mi][nj][2] + b2v.x, acc[mi][nj][3] + b2v.y);
                    *reinterpret_cast<unsigned*>(C + (size_t)r1 * mCols + c) = *reinterpret_cast<unsigned*>(&h);
                }
            }
        }
    }
}

// ---------------- GRU gates (fp16 inputs) ----------------
__device__ __forceinline__ float sigf(float x) { return 1.f / (1.f + expf(-x)); }

__global__ void k_gate(const float* __restrict__ A, float* __restrict__ out) {
    int gid = blockIdx.x * blockDim.x + threadIdx.x;
    int node = gid >> 5, lane = gid & 31;
    if (node >= N_NODES) return;
    const uint2* gi = reinterpret_cast<const uint2*>(g_gih + (size_t)node * 384);
    const uint2* gh = reinterpret_cast<const uint2*>(g_ghh + (size_t)node * 384);
    float4 gir = h4_to_f4(gi[lane]), giz = h4_to_f4(gi[32 + lane]), gin = h4_to_f4(gi[64 + lane]);
    float4 ghr = h4_to_f4(gh[lane]), ghz = h4_to_f4(gh[32 + lane]), ghn = h4_to_f4(gh[64 + lane]);
    float4 h = reinterpret_cast<const float4*>(A)[node * 32 + lane];
    float4 res;
    { float r = sigf(gir.x + ghr.x), z = sigf(giz.x + ghz.x);
      float n = tanhf(gin.x + r * ghn.x); res.x = (1.f - z) * n + z * h.x; }
    { float r = sigf(gir.y + ghr.y), z = sigf(giz.y + ghz.y);
      float n = tanhf(gin.y + r * ghn.y); res.y = (1.f - z) * n + z * h.y; }
    { float r = sigf(gir.z + ghr.z), z = sigf(giz.z + ghz.z);
      float n = tanhf(gin.z + r * ghn.z); res.z = (1.f - z) * n + z * h.z; }
    { float r = sigf(gir.w + ghr.w), z = sigf(giz.w + ghz.w);
      float n = tanhf(gin.w + r * ghn.w); res.w = (1.f - z) * n + z * h.w; }
    reinterpret_cast<float4*>(out)[node * 32 + lane] = res;
}

// ---------------- launch ----------------
extern "C" void kernel_launch(void* const* d_in, const int* in_sizes, int n_in,
                              void* d_out, int out_size) {
    const float* A    = (const float*)d_in[0];
    const float* W1   = (const float*)d_in[1];
    const float* b1   = (const float*)d_in[2];
    const float* W2   = (const float*)d_in[3];
    const float* b2   = (const float*)d_in[4];
    const float* w_ih = (const float*)d_in[5];
    const float* w_hh = (const float*)d_in[6];
    const float* b_ih = (const float*)d_in[7];
    const float* b_hh = (const float*)d_in[8];
    const void*  ei   = d_in[9];
    float* out = (float*)d_out;

    cudaFuncSetAttribute(k_hmma, cudaFuncAttributeMaxDynamicSharedMemorySize, SM_TOTAL);

    constexpr int RT = (N_NODES + 127) / 128;       // 782 row slabs
    constexpr int NODE_BLKS = (N_NODES + 255) / 256;
    constexpr int EDGE_BLKS = (N_EDGES + 255) / 256;
    constexpr int WARP_BLKS = (N_NODES * 32 + 255) / 256;
    constexpr int CVTW_BLKS = ((128 + 384 + 384) * 32 + 255) / 256;

    k_zero<<<NODE_BLKS, 256>>>((const int*)ei);
    k_logits<<<WARP_BLKS, 256>>>(A, W1);                          // also produces g_ah
    k_cvtW<<<CVTW_BLKS, 256>>>(W2, w_ih, w_hh);
    k_hmma<<<RT, 256, SM_TOTAL>>>(0, b2, b_ih, b_hh);             // nft + gh (edge-independent)
    k_count<<<EDGE_BLKS, 256>>>(ei);
    k_alloc<<<NODE_BLKS, 256>>>();
    k_fill<<<EDGE_BLKS, 256>>>(ei, b1);
    k_agg<<<WARP_BLKS, 256>>>(A);
    k_hmma<<<RT, 256, SM_TOTAL>>>(1, b2, b_ih, b_hh);             // gi
    k_gate<<<WARP_BLKS, 256>>>(A, out);
}

// round 13
// speedup vs baseline: 1.0196x; 1.0196x over previous
#include <cuda_runtime.h>
#include <cuda_fp16.h>
#include <math.h>

static constexpr int N_NODES = 100000;
static constexpr int N_EDGES = 1600000;
static constexpr int D = 128;

// ---------------- scratch (device globals; no runtime allocation) ----------------
__device__ __align__(16) __half g_nft[N_NODES * D];       // fp16: A@W2^T + b2
__device__ __align__(16) __half g_gih[N_NODES * 384];     // fp16 gate pre-activations
__device__ __align__(16) __half g_ghh[N_NODES * 384];
__device__ __align__(16) __half g_ah[N_NODES * D];        // A in fp16 (RN)
__device__ __align__(16) __half g_oh[N_NODES * D];        // out_emb in fp16 (RN)
__device__ __align__(16) __half g_w2[128 * D];            // weights fp16
__device__ __align__(16) __half g_wih[384 * D];
__device__ __align__(16) __half g_whh[384 * D];
__device__ float g_logit[N_NODES];
__device__ float g_logit_src[N_NODES];
__device__ int   g_cnt[N_NODES];
__device__ int   g_start[N_NODES];
__device__ int   g_cursor[N_NODES];
__device__ __align__(8) int2 g_pack[N_EDGES];             // {src, bits(exp(score))}
__device__ int   g_counter;
__device__ int   g_is64;

// ---------------- fp16 helpers ----------------
__device__ __forceinline__ void cvt4_h(float4 v, __half* dst, long long i4) {
    __half2 p0 = __floats2half2_rn(v.x, v.y);
    __half2 p1 = __floats2half2_rn(v.z, v.w);
    uint2 u;
    u.x = *reinterpret_cast<unsigned*>(&p0);
    u.y = *reinterpret_cast<unsigned*>(&p1);
    reinterpret_cast<uint2*>(dst)[i4] = u;
}
__device__ __forceinline__ float4 h4_to_f4(uint2 u) {
    __half2 a = *reinterpret_cast<__half2*>(&u.x);
    __half2 b = *reinterpret_cast<__half2*>(&u.y);
    float2 fa = __half22float2(a), fb = __half22float2(b);
    return make_float4(fa.x, fa.y, fb.x, fb.y);
}

// dtype-adaptive edge index load, clamped to [0, N_NODES).
__device__ __forceinline__ int load_idx(const void* ei, long long i, int is64) {
    long long v = is64 ? reinterpret_cast<const long long*>(ei)[i]
                       : (long long)reinterpret_cast<const int*>(ei)[i];
    v = v < 0 ? 0 : (v >= N_NODES ? N_NODES - 1 : v);
    return (int)v;
}

// ---------------- small kernels ----------------
__global__ void k_zero(const int* __restrict__ eiw) {
    int i = blockIdx.x * blockDim.x + threadIdx.x;
    if (i < N_NODES) g_cnt[i] = 0;
    if (i == 0) {
        g_counter = 0;
        g_is64 = (eiw[1] == 0 && eiw[3] == 0 && eiw[5] == 0 && eiw[7] == 0) ? 1 : 0;
    }
}

__global__ void k_cvtW(const float* __restrict__ W2, const float* __restrict__ wih,
                       const float* __restrict__ whh) {
    int i = blockIdx.x * blockDim.x + threadIdx.x;
    const int n2 = 128 * 32, nih = 384 * 32;
    if (i < n2)
        cvt4_h(reinterpret_cast<const float4*>(W2)[i], g_w2, i);
    else if (i < n2 + nih)
        cvt4_h(reinterpret_cast<const float4*>(wih)[i - n2], g_wih, i - n2);
    else if (i < n2 + 2 * nih)
        cvt4_h(reinterpret_cast<const float4*>(whh)[i - n2 - nih], g_whh, i - n2 - nih);
}

// merged: per-node logits AND fp16 conversion of A (single pass over A)
__global__ void k_logits(const float* __restrict__ A, const float* __restrict__ W1) {
    int gid = blockIdx.x * blockDim.x + threadIdx.x;
    int node = gid >> 5, lane = gid & 31;
    if (node >= N_NODES) return;
    float4 x  = reinterpret_cast<const float4*>(A)[node * 32 + lane];
    cvt4_h(x, g_ah, (long long)node * 32 + lane);
    float4 wd = __ldg(reinterpret_cast<const float4*>(W1) + lane);
    float4 ws = __ldg(reinterpret_cast<const float4*>(W1) + 32 + lane);
    float d = x.x * wd.x + x.y * wd.y + x.z * wd.z + x.w * wd.w;
    float s = x.x * ws.x + x.y * ws.y + x.z * ws.z + x.w * ws.w;
#pragma unroll
    for (int o = 16; o; o >>= 1) {
        d += __shfl_xor_sync(0xffffffffu, d, o);
        s += __shfl_xor_sync(0xffffffffu, s, o);
    }
    if (lane == 0) { g_logit[node] = d; g_logit_src[node] = s; }
}

__global__ void k_count(const void* __restrict__ ei) {
    int e = blockIdx.x * blockDim.x + threadIdx.x;
    if (e >= N_EDGES) return;
    atomicAdd(&g_cnt[load_idx(ei, (long long)N_EDGES + e, g_is64)], 1);
}

__global__ void k_alloc() {
    int n = blockIdx.x * blockDim.x + threadIdx.x;
    if (n >= N_NODES) return;
    int c = g_cnt[n];
    int s = atomicAdd(&g_counter, c);
    g_start[n] = s;
    g_cursor[n] = s;
}

// segment_max elided: cancels exactly in attn = e/denom; scores are O(1).
__global__ void k_fill(const void* __restrict__ ei, const float* __restrict__ b1) {
    int e = blockIdx.x * blockDim.x + threadIdx.x;
    if (e >= N_EDGES) return;
    int is64 = g_is64;
    int src = load_idx(ei, e, is64);
    int dst = load_idx(ei, (long long)N_EDGES + e, is64);
    float sc = g_logit[dst] + g_logit_src[src] + __ldg(b1);
    sc = sc > 0.f ? sc : 0.2f * sc;
    float es = expf(sc);
    int pos = atomicAdd(&g_cursor[dst], 1);
    if (pos < N_EDGES) g_pack[pos] = make_int2(src, __float_as_int(es));
}

// warp per node: denom + weighted gather (fp16 nft) + ELU + deg select; writes fp16 oemb
__global__ void k_agg(const float* __restrict__ A) {
    int gid = blockIdx.x * blockDim.x + threadIdx.x;
    int node = gid >> 5, lane = gid & 31;
    if (node >= N_NODES) return;
    int s0 = g_start[node];
    int len = g_cnt[node];
    if (s0 + len > N_EDGES) len = N_EDGES - s0 > 0 ? N_EDGES - s0 : 0;

    float dsum = 0.f;
    for (int t = lane; t < len; t += 32) dsum += __int_as_float(g_pack[s0 + t].y);
#pragma unroll
    for (int o = 16; o; o >>= 1) dsum += __shfl_xor_sync(0xffffffffu, dsum, o);

    float4 out;
    if (len > 0) {
        float inv = 1.f / dsum;
        float ax = 0.f, ay = 0.f, az = 0.f, aw = 0.f;
        const uint2* nf = reinterpret_cast<const uint2*>(g_nft);
#pragma unroll 2
        for (int t = 0; t < len; ++t) {
            int2 p = g_pack[s0 + t];
            float w = __int_as_float(p.y) * inv;
            float4 v = h4_to_f4(nf[(size_t)p.x * 32 + lane]);
            ax = fmaf(w, v.x, ax); ay = fmaf(w, v.y, ay);
            az = fmaf(w, v.z, az); aw = fmaf(w, v.w, aw);
        }
        out.x = ax > 0.f ? ax : (expf(ax) - 1.f);
        out.y = ay > 0.f ? ay : (expf(ay) - 1.f);
        out.z = az > 0.f ? az : (expf(az) - 1.f);
        out.w = aw > 0.f ? aw : (expf(aw) - 1.f);
    } else {
        out = reinterpret_cast<const float4*>(A)[node * 32 + lane];
    }
    cvt4_h(out, g_oh, (long long)node * 32 + lane);
}

// ---------------- HMMA GEMM (fp16 mma.sync, 64x128 tile, 3 CTAs/SM) ----
// C = X_fp16 . W_fp16^T + bias ; fp16 output.
// Tile M=64, N=128. 8 warps in 2x4; warp tile 32x32 -> 32 fp32 acc/thread,
// ~80 regs -> 24 warps/SM (vs 16 at 128x128), better HMMA latency hiding.
// smem row = 256B (16 chunks of 16B), phys chunk = ch ^ (row&7).

static constexpr int SM_X  = 0;        // 64 rows * 256B = 16 KB
static constexpr int SM_W  = 16384;    // 128 rows * 256B = 32 KB
static constexpr int SM_TOTAL = 49152;

__device__ __forceinline__ unsigned smem_u32(const void* p) {
    unsigned a;
    asm("{ .reg .u64 t; cvta.to.shared.u64 t, %1; cvt.u32.u64 %0, t; }" : "=r"(a) : "l"(p));
    return a;
}
__device__ __forceinline__ void cpasync16(unsigned dst, const void* src, bool valid) {
    int sz = valid ? 16 : 0;
    asm volatile("cp.async.cg.shared.global [%0], [%1], 16, %2;"
                 :: "r"(dst), "l"(src), "r"(sz) : "memory");
}
__device__ __forceinline__ void ldsm4(unsigned& r0, unsigned& r1, unsigned& r2, unsigned& r3, unsigned a) {
    asm volatile("ldmatrix.sync.aligned.m8n8.x4.shared.b16 {%0,%1,%2,%3}, [%4];"
                 : "=r"(r0), "=r"(r1), "=r"(r2), "=r"(r3) : "r"(a));
}
__device__ __forceinline__ void mma16816(float* c, unsigned a0, unsigned a1, unsigned a2, unsigned a3,
                                         unsigned b0, unsigned b1) {
    asm volatile("mma.sync.aligned.m16n8k16.row.col.f32.f16.f16.f32 "
                 "{%0,%1,%2,%3}, {%4,%5,%6,%7}, {%8,%9}, {%0,%1,%2,%3};"
                 : "+f"(c[0]), "+f"(c[1]), "+f"(c[2]), "+f"(c[3])
                 : "r"(a0), "r"(a1), "r"(a2), "r"(a3), "r"(b0), "r"(b1));
}

__global__ __launch_bounds__(256, 3) void k_hmma(
    int mode,                     // 0 = nft+gh (grid RTM x 4), 1 = gi (grid RTM x 3)
    const float* __restrict__ b2,
    const float* __restrict__ bih,
    const float* __restrict__ bhh)
{
    extern __shared__ __align__(128) char smem[];
    const int tid = threadIdx.x, wid = tid >> 5, lane = tid & 31;
    const unsigned sb = smem_u32(smem);
    const int rowBase = blockIdx.x * 64;

    const __half *Xp, *Wp;
    const float* bias;
    __half* C;
    int mCols, colBase;
    if (mode == 0) {
        int y = blockIdx.y;
        if (y == 0) { Xp = g_ah; Wp = g_w2;  bias = b2;  C = g_nft; mCols = 128; colBase = 0; }
        else        { Xp = g_ah; Wp = g_whh; bias = bhh; C = g_ghh; mCols = 384; colBase = (y - 1) * 128; }
    } else {
        Xp = g_oh; Wp = g_wih; bias = bih; C = g_gih; mCols = 384; colBase = blockIdx.y * 128;
    }
    const __half* Wcol = Wp + (size_t)colBase * 128;

    // ---- tile loads: X (64 rows) + W (128 rows) in one async group ----
#pragma unroll
    for (int it = 0; it < 4; ++it) {
        int lc  = it * 256 + tid;        // 0..1023
        int row = lc >> 4;
        int ch  = lc & 15;
        unsigned so = (unsigned)(row * 256 + ((ch ^ (row & 7)) << 4));
        int gr = rowBase + row;
        cpasync16(sb + SM_X + so, Xp + (size_t)gr * 128 + ch * 8, gr < N_NODES);
    }
#pragma unroll
    for (int it = 0; it < 8; ++it) {
        int lc  = it * 256 + tid;        // 0..2047
        int row = lc >> 4;
        int ch  = lc & 15;
        unsigned so = (unsigned)(row * 256 + ((ch ^ (row & 7)) << 4));
        cpasync16(sb + SM_W + so, Wcol + (size_t)row * 128 + ch * 8, true);
    }
    asm volatile("cp.async.commit_group;" ::: "memory");

    const int warpRow = (wid >> 2) * 32;   // 0 or 32
    const int warpCol = (wid & 3) * 32;    // 0,32,64,96
    const int arow = warpRow + (lane & 15);
    const int ahalf = lane >> 4;
    const int bn = warpCol + ((lane >> 4) << 3) + (lane & 7);
    const int bhalf = (lane >> 3) & 1;

    float acc[2][4][4];
#pragma unroll
    for (int mi = 0; mi < 2; ++mi)
#pragma unroll
        for (int nj = 0; nj < 4; ++nj)
#pragma unroll
            for (int q = 0; q < 4; ++q) acc[mi][nj][q] = 0.f;

    asm volatile("cp.async.wait_group 0;" ::: "memory");
    __syncthreads();

    const unsigned ab = sb + SM_X;
    const unsigned bb = sb + SM_W;
#pragma unroll
    for (int s = 0; s < 8; ++s) {
        unsigned a[2][4];
#pragma unroll
        for (int mi = 0; mi < 2; ++mi) {
            int r = arow + mi * 16;
            unsigned ch = (unsigned)((2 * s + ahalf) ^ (r & 7));
            ldsm4(a[mi][0], a[mi][1], a[mi][2], a[mi][3], ab + r * 256 + (ch << 4));
        }
        unsigned b[2][4];
#pragma unroll
        for (int q = 0; q < 2; ++q) {
            int n = bn + q * 16;
            unsigned ch = (unsigned)((2 * s + bhalf) ^ (n & 7));
            ldsm4(b[q][0], b[q][1], b[q][2], b[q][3], bb + n * 256 + (ch << 4));
        }
#pragma unroll
        for (int mi = 0; mi < 2; ++mi) {
#pragma unroll
            for (int nj = 0; nj < 4; ++nj) {
                unsigned b0 = b[nj >> 1][(nj & 1) * 2];
                unsigned b1 = b[nj >> 1][(nj & 1) * 2 + 1];
                mma16816(acc[mi][nj], a[mi][0], a[mi][1], a[mi][2], a[mi][3], b0, b1);
            }
        }
    }

    // ---- epilogue: bias + fp16 store ----
    const int colOff = colBase + warpCol + 2 * (lane & 3);
#pragma unroll
    for (int nj = 0; nj < 4; ++nj) {
        int c = colOff + nj * 8;
        float2 b2v = __ldg(reinterpret_cast<const float2*>(bias + c));
#pragma unroll
        for (int mi = 0; mi < 2; ++mi) {
            int r0 = rowBase + warpRow + mi * 16 + (lane >> 2);
            if (r0 < N_NODES) {
                __half2 h = __floats2half2_rn(acc[mi][nj][0] + b2v.x, acc[mi][nj][1] + b2v.y);
                *reinterpret_cast<unsigned*>(C + (size_t)r0 * mCols + c) = *reinterpret_cast<unsigned*>(&h);
            }
            int r1 = r0 + 8;
            if (r1 < N_NODES) {
                __half2 h = __floats2half2_rn(acc[mi][nj][2] + b2v.x, acc[mi][nj][3] + b2v.y);
                *reinterpret_cast<unsigned*>(C + (size_t)r1 * mCols + c) = *reinterpret_cast<unsigned*>(&h);
            }
        }
    }
}

// ---------------- GRU gates (fp16 inputs) ----------------
__device__ __forceinline__ float sigf(float x) { return 1.f / (1.f + expf(-x)); }

__global__ void k_gate(const float* __restrict__ A, float* __restrict__ out) {
    int gid = blockIdx.x * blockDim.x + threadIdx.x;
    int node = gid >> 5, lane = gid & 31;
    if (node >= N_NODES) return;
    const uint2* gi = reinterpret_cast<const uint2*>(g_gih + (size_t)node * 384);
    const uint2* gh = reinterpret_cast<const uint2*>(g_ghh + (size_t)node * 384);
    float4 gir = h4_to_f4(gi[lane]), giz = h4_to_f4(gi[32 + lane]), gin = h4_to_f4(gi[64 + lane]);
    float4 ghr = h4_to_f4(gh[lane]), ghz = h4_to_f4(gh[32 + lane]), ghn = h4_to_f4(gh[64 + lane]);
    float4 h = reinterpret_cast<const float4*>(A)[node * 32 + lane];
    float4 res;
    { float r = sigf(gir.x + ghr.x), z = sigf(giz.x + ghz.x);
      float n = tanhf(gin.x + r * ghn.x); res.x = (1.f - z) * n + z * h.x; }
    { float r = sigf(gir.y + ghr.y), z = sigf(giz.y + ghz.y);
      float n = tanhf(gin.y + r * ghn.y); res.y = (1.f - z) * n + z * h.y; }
    { float r = sigf(gir.z + ghr.z), z = sigf(giz.z + ghz.z);
      float n = tanhf(gin.z + r * ghn.z); res.z = (1.f - z) * n + z * h.z; }
    { float r = sigf(gir.w + ghr.w), z = sigf(giz.w + ghz.w);
      float n = tanhf(gin.w + r * ghn.w); res.w = (1.f - z) * n + z * h.w; }
    reinterpret_cast<float4*>(out)[node * 32 + lane] = res;
}

// ---------------- launch ----------------
extern "C" void kernel_launch(void* const* d_in, const int* in_sizes, int n_in,
                              void* d_out, int out_size) {
    const float* A    = (const float*)d_in[0];
    const float* W1   = (const float*)d_in[1];
    const float* b1   = (const float*)d_in[2];
    const float* W2   = (const float*)d_in[3];
    const float* b2   = (const float*)d_in[4];
    const float* w_ih = (const float*)d_in[5];
    const float* w_hh = (const float*)d_in[6];
    const float* b_ih = (const float*)d_in[7];
    const float* b_hh = (const float*)d_in[8];
    const void*  ei   = d_in[9];
    float* out = (float*)d_out;

    cudaFuncSetAttribute(k_hmma, cudaFuncAttributeMaxDynamicSharedMemorySize, SM_TOTAL);

    constexpr int RTM = (N_NODES + 63) / 64;        // 1563 row tiles (M=64)
    constexpr int NODE_BLKS = (N_NODES + 255) / 256;
    constexpr int EDGE_BLKS = (N_EDGES + 255) / 256;
    constexpr int WARP_BLKS = (N_NODES * 32 + 255) / 256;
    constexpr int CVTW_BLKS = ((128 + 384 + 384) * 32 + 255) / 256;

    k_zero<<<NODE_BLKS, 256>>>((const int*)ei);
    k_logits<<<WARP_BLKS, 256>>>(A, W1);                          // also produces g_ah
    k_cvtW<<<CVTW_BLKS, 256>>>(W2, w_ih, w_hh);
    k_hmma<<<dim3(RTM, 4), 256, SM_TOTAL>>>(0, b2, b_ih, b_hh);   // nft + gh (edge-independent)
    k_count<<<EDGE_BLKS, 256>>>(ei);
    k_alloc<<<NODE_BLKS, 256>>>();
    k_fill<<<EDGE_BLKS, 256>>>(ei, b1);
    k_agg<<<WARP_BLKS, 256>>>(A);
    k_hmma<<<dim3(RTM, 3), 256, SM_TOTAL>>>(1, b2, b_ih, b_hh);   // gi
    k_gate<<<WARP_BLKS, 256>>>(A, out);
}

// round 14
// speedup vs baseline: 1.0494x; 1.0292x over previous
#include <cuda_runtime.h>
#include <cuda_fp16.h>
#include <math.h>

static constexpr int N_NODES = 100000;
static constexpr int N_EDGES = 1600000;
static constexpr int D = 128;

// ---------------- scratch (device globals; no runtime allocation) ----------------
__device__ __align__(16) __half g_nft[N_NODES * D];       // fp16: A@W2^T + b2
__device__ __align__(16) __half g_gih[N_NODES * 384];     // fp16 gate pre-activations
__device__ __align__(16) __half g_ghh[N_NODES * 384];
__device__ __align__(16) __half g_ah[N_NODES * D];        // A in fp16 (RN)
__device__ __align__(16) __half g_oh[N_NODES * D];        // out_emb in fp16 (RN)
__device__ __align__(16) __half g_w2[128 * D];            // weights fp16
__device__ __align__(16) __half g_wih[384 * D];
__device__ __align__(16) __half g_whh[384 * D];
__device__ float g_logit[N_NODES];
__device__ float g_logit_src[N_NODES];
__device__ int   g_cnt[N_NODES];
__device__ int   g_start[N_NODES];
__device__ int   g_cursor[N_NODES];
__device__ __align__(8) int2 g_pack[N_EDGES];             // {src, bits(exp(score))}
__device__ int   g_counter;
__device__ int   g_is64;

// ---------------- fp16 helpers ----------------
__device__ __forceinline__ void cvt4_h(float4 v, __half* dst, long long i4) {
    __half2 p0 = __floats2half2_rn(v.x, v.y);
    __half2 p1 = __floats2half2_rn(v.z, v.w);
    uint2 u;
    u.x = *reinterpret_cast<unsigned*>(&p0);
    u.y = *reinterpret_cast<unsigned*>(&p1);
    reinterpret_cast<uint2*>(dst)[i4] = u;
}
__device__ __forceinline__ float4 h4_to_f4(uint2 u) {
    __half2 a = *reinterpret_cast<__half2*>(&u.x);
    __half2 b = *reinterpret_cast<__half2*>(&u.y);
    float2 fa = __half22float2(a), fb = __half22float2(b);
    return make_float4(fa.x, fa.y, fb.x, fb.y);
}

// dtype-adaptive edge index load, clamped to [0, N_NODES).
__device__ __forceinline__ int load_idx(const void* ei, long long i, int is64) {
    long long v = is64 ? reinterpret_cast<const long long*>(ei)[i]
                       : (long long)reinterpret_cast<const int*>(ei)[i];
    v = v < 0 ? 0 : (v >= N_NODES ? N_NODES - 1 : v);
    return (int)v;
}

// ---------------- small kernels ----------------
__global__ void k_zero(const int* __restrict__ eiw) {
    int i = blockIdx.x * blockDim.x + threadIdx.x;
    if (i < N_NODES) g_cnt[i] = 0;
    if (i == 0) {
        g_counter = 0;
        g_is64 = (eiw[1] == 0 && eiw[3] == 0 && eiw[5] == 0 && eiw[7] == 0) ? 1 : 0;
    }
}

__global__ void k_cvtW(const float* __restrict__ W2, const float* __restrict__ wih,
                       const float* __restrict__ whh) {
    int i = blockIdx.x * blockDim.x + threadIdx.x;
    const int n2 = 128 * 32, nih = 384 * 32;
    if (i < n2)
        cvt4_h(reinterpret_cast<const float4*>(W2)[i], g_w2, i);
    else if (i < n2 + nih)
        cvt4_h(reinterpret_cast<const float4*>(wih)[i - n2], g_wih, i - n2);
    else if (i < n2 + 2 * nih)
        cvt4_h(reinterpret_cast<const float4*>(whh)[i - n2 - nih], g_whh, i - n2 - nih);
}

// merged: per-node logits AND fp16 conversion of A (single pass over A)
__global__ void k_logits(const float* __restrict__ A, const float* __restrict__ W1) {
    int gid = blockIdx.x * blockDim.x + threadIdx.x;
    int node = gid >> 5, lane = gid & 31;
    if (node >= N_NODES) return;
    float4 x  = reinterpret_cast<const float4*>(A)[node * 32 + lane];
    cvt4_h(x, g_ah, (long long)node * 32 + lane);
    float4 wd = __ldg(reinterpret_cast<const float4*>(W1) + lane);
    float4 ws = __ldg(reinterpret_cast<const float4*>(W1) + 32 + lane);
    float d = x.x * wd.x + x.y * wd.y + x.z * wd.z + x.w * wd.w;
    float s = x.x * ws.x + x.y * ws.y + x.z * ws.z + x.w * ws.w;
#pragma unroll
    for (int o = 16; o; o >>= 1) {
        d += __shfl_xor_sync(0xffffffffu, d, o);
        s += __shfl_xor_sync(0xffffffffu, s, o);
    }
    if (lane == 0) { g_logit[node] = d; g_logit_src[node] = s; }
}

__global__ void k_count(const void* __restrict__ ei) {
    int e = blockIdx.x * blockDim.x + threadIdx.x;
    if (e >= N_EDGES) return;
    atomicAdd(&g_cnt[load_idx(ei, (long long)N_EDGES + e, g_is64)], 1);
}

__global__ void k_alloc() {
    int n = blockIdx.x * blockDim.x + threadIdx.x;
    if (n >= N_NODES) return;
    int c = g_cnt[n];
    int s = atomicAdd(&g_counter, c);
    g_start[n] = s;
    g_cursor[n] = s;
}

// segment_max elided: cancels exactly in attn = e/denom; scores are O(1).
__global__ void k_fill(const void* __restrict__ ei, const float* __restrict__ b1) {
    int e = blockIdx.x * blockDim.x + threadIdx.x;
    if (e >= N_EDGES) return;
    int is64 = g_is64;
    int src = load_idx(ei, e, is64);
    int dst = load_idx(ei, (long long)N_EDGES + e, is64);
    float sc = g_logit[dst] + g_logit_src[src] + __ldg(b1);
    sc = sc > 0.f ? sc : 0.2f * sc;
    float es = expf(sc);
    int pos = atomicAdd(&g_cursor[dst], 1);
    if (pos < N_EDGES) g_pack[pos] = make_int2(src, __float_as_int(es));
}

// warp per node, SINGLE PASS: accumulate Sum(w*v) and Sum(w) together,
// normalize once at the end. ELU + deg select; writes fp16 oemb.
__global__ void k_agg(const float* __restrict__ A) {
    int gid = blockIdx.x * blockDim.x + threadIdx.x;
    int node = gid >> 5, lane = gid & 31;
    if (node >= N_NODES) return;
    int s0 = g_start[node];
    int len = g_cnt[node];
    if (s0 + len > N_EDGES) len = N_EDGES - s0 > 0 ? N_EDGES - s0 : 0;

    float4 out;
    if (len > 0) {
        float dsum = 0.f;
        float ax = 0.f, ay = 0.f, az = 0.f, aw = 0.f;
        const uint2* nf = reinterpret_cast<const uint2*>(g_nft);
#pragma unroll 2
        for (int t = 0; t < len; ++t) {
            int2 p = g_pack[s0 + t];
            float w = __int_as_float(p.y);
            dsum += w;
            float4 v = h4_to_f4(nf[(size_t)p.x * 32 + lane]);
            ax = fmaf(w, v.x, ax); ay = fmaf(w, v.y, ay);
            az = fmaf(w, v.z, az); aw = fmaf(w, v.w, aw);
        }
        float inv = 1.f / dsum;
        ax *= inv; ay *= inv; az *= inv; aw *= inv;
        out.x = ax > 0.f ? ax : (expf(ax) - 1.f);
        out.y = ay > 0.f ? ay : (expf(ay) - 1.f);
        out.z = az > 0.f ? az : (expf(az) - 1.f);
        out.w = aw > 0.f ? aw : (expf(aw) - 1.f);
    } else {
        out = reinterpret_cast<const float4*>(A)[node * 32 + lane];
    }
    cvt4_h(out, g_oh, (long long)node * 32 + lane);
}

// ---------------- HMMA GEMM (fp16 mma.sync, 128x128 tile, 2 CTAs/SM, pipelined) ----
// C = X_fp16 . W_fp16^T + bias ; fp16 output.
// 8 warps (2x4), warp tile 64x32. k-step loop software-pipelined: fragments for
// step s+1 LDSM'd while step s's 16 HMMAs run (double-buffered frag regs).
// smem row = 256B (16 chunks of 16B), phys chunk = ch ^ (row&7).

static constexpr int SM_X = 0;
static constexpr int SM_W = 32768;
static constexpr int SM_TOTAL = 65536;

__device__ __forceinline__ unsigned smem_u32(const void* p) {
    unsigned a;
    asm("{ .reg .u64 t; cvta.to.shared.u64 t, %1; cvt.u32.u64 %0, t; }" : "=r"(a) : "l"(p));
    return a;
}
__device__ __forceinline__ void cpasync16(unsigned dst, const void* src, bool valid) {
    int sz = valid ? 16 : 0;
    asm volatile("cp.async.cg.shared.global [%0], [%1], 16, %2;"
                 :: "r"(dst), "l"(src), "r"(sz) : "memory");
}
__device__ __forceinline__ void ldsm4(unsigned& r0, unsigned& r1, unsigned& r2, unsigned& r3, unsigned a) {
    asm volatile("ldmatrix.sync.aligned.m8n8.x4.shared.b16 {%0,%1,%2,%3}, [%4];"
                 : "=r"(r0), "=r"(r1), "=r"(r2), "=r"(r3) : "r"(a));
}
__device__ __forceinline__ void mma16816(float* c, unsigned a0, unsigned a1, unsigned a2, unsigned a3,
                                         unsigned b0, unsigned b1) {
    asm volatile("mma.sync.aligned.m16n8k16.row.col.f32.f16.f16.f32 "
                 "{%0,%1,%2,%3}, {%4,%5,%6,%7}, {%8,%9}, {%0,%1,%2,%3};"
                 : "+f"(c[0]), "+f"(c[1]), "+f"(c[2]), "+f"(c[3])
                 : "r"(a0), "r"(a1), "r"(a2), "r"(a3), "r"(b0), "r"(b1));
}

__global__ __launch_bounds__(256, 2) void k_hmma(
    int mode,                     // 0 = nft+gh (grid RT x 4), 1 = gi (grid RT x 3)
    const float* __restrict__ b2,
    const float* __restrict__ bih,
    const float* __restrict__ bhh)
{
    extern __shared__ __align__(128) char smem[];
    const int tid = threadIdx.x, wid = tid >> 5, lane = tid & 31;
    const unsigned sb = smem_u32(smem);
    const int rowBase = blockIdx.x * 128;

    const __half *Xp, *Wp;
    const float* bias;
    __half* C;
    int mCols, colBase;
    if (mode == 0) {
        int y = blockIdx.y;
        if (y == 0) { Xp = g_ah; Wp = g_w2;  bias = b2;  C = g_nft; mCols = 128; colBase = 0; }
        else        { Xp = g_ah; Wp = g_whh; bias = bhh; C = g_ghh; mCols = 384; colBase = (y - 1) * 128; }
    } else {
        Xp = g_oh; Wp = g_wih; bias = bih; C = g_gih; mCols = 384; colBase = blockIdx.y * 128;
    }
    const __half* Wcol = Wp + (size_t)colBase * 128;

    // ---- tile loads: X + W in one async group ----
#pragma unroll
    for (int it = 0; it < 8; ++it) {
        int lc  = it * 256 + tid;        // 0..2047
        int row = lc >> 4;
        int ch  = lc & 15;
        unsigned so = (unsigned)(row * 256 + ((ch ^ (row & 7)) << 4));
        int gr = rowBase + row;
        cpasync16(sb + SM_X + so, Xp + (size_t)gr * 128 + ch * 8, gr < N_NODES);
        cpasync16(sb + SM_W + so, Wcol + (size_t)row * 128 + ch * 8, true);
    }
    asm volatile("cp.async.commit_group;" ::: "memory");

    const int warpRow = (wid >> 2) * 64;   // 0 or 64
    const int warpCol = (wid & 3) * 32;    // 0,32,64,96
    const int arow = warpRow + (lane & 15);
    const int ahalf = lane >> 4;
    const int bn = warpCol + ((lane >> 4) << 3) + (lane & 7);
    const int bhalf = (lane >> 3) & 1;

    float acc[4][4][4];
#pragma unroll
    for (int mi = 0; mi < 4; ++mi)
#pragma unroll
        for (int nj = 0; nj < 4; ++nj)
#pragma unroll
            for (int q = 0; q < 4; ++q) acc[mi][nj][q] = 0.f;

    asm volatile("cp.async.wait_group 0;" ::: "memory");
    __syncthreads();

    const unsigned ab = sb + SM_X;
    const unsigned bb = sb + SM_W;

    // double-buffered fragments: load s, prefetch s+1 while computing s
    unsigned a[2][4][4], b[2][2][4];
#pragma unroll
    for (int mi = 0; mi < 4; ++mi) {
        int r = arow + mi * 16;
        unsigned ch = (unsigned)(ahalf ^ (r & 7));
        ldsm4(a[0][mi][0], a[0][mi][1], a[0][mi][2], a[0][mi][3], ab + r * 256 + (ch << 4));
    }
#pragma unroll
    for (int q = 0; q < 2; ++q) {
        int n = bn + q * 16;
        unsigned ch = (unsigned)(bhalf ^ (n & 7));
        ldsm4(b[0][q][0], b[0][q][1], b[0][q][2], b[0][q][3], bb + n * 256 + (ch << 4));
    }

#pragma unroll
    for (int s = 0; s < 8; ++s) {
        const int cur = s & 1, nxt = cur ^ 1;
        if (s < 7) {
#pragma unroll
            for (int mi = 0; mi < 4; ++mi) {
                int r = arow + mi * 16;
                unsigned ch = (unsigned)((2 * (s + 1) + ahalf) ^ (r & 7));
                ldsm4(a[nxt][mi][0], a[nxt][mi][1], a[nxt][mi][2], a[nxt][mi][3],
                      ab + r * 256 + (ch << 4));
            }
#pragma unroll
            for (int q = 0; q < 2; ++q) {
                int n = bn + q * 16;
                unsigned ch = (unsigned)((2 * (s + 1) + bhalf) ^ (n & 7));
                ldsm4(b[nxt][q][0], b[nxt][q][1], b[nxt][q][2], b[nxt][q][3],
                      bb + n * 256 + (ch << 4));
            }
        }
#pragma unroll
        for (int mi = 0; mi < 4; ++mi) {
#pragma unroll
            for (int nj = 0; nj < 4; ++nj) {
                unsigned b0 = b[cur][nj >> 1][(nj & 1) * 2];
                unsigned b1 = b[cur][nj >> 1][(nj & 1) * 2 + 1];
                mma16816(acc[mi][nj], a[cur][mi][0], a[cur][mi][1], a[cur][mi][2], a[cur][mi][3], b0, b1);
            }
        }
    }

    // ---- epilogue: bias + fp16 store ----
    const int colOff = colBase + warpCol + 2 * (lane & 3);
#pragma unroll
    for (int nj = 0; nj < 4; ++nj) {
        int c = colOff + nj * 8;
        float2 b2v = __ldg(reinterpret_cast<const float2*>(bias + c));
#pragma unroll
        for (int mi = 0; mi < 4; ++mi) {
            int r0 = rowBase + warpRow + mi * 16 + (lane >> 2);
            if (r0 < N_NODES) {
                __half2 h = __floats2half2_rn(acc[mi][nj][0] + b2v.x, acc[mi][nj][1] + b2v.y);
                *reinterpret_cast<unsigned*>(C + (size_t)r0 * mCols + c) = *reinterpret_cast<unsigned*>(&h);
            }
            int r1 = r0 + 8;
            if (r1 < N_NODES) {
                __half2 h = __floats2half2_rn(acc[mi][nj][2] + b2v.x, acc[mi][nj][3] + b2v.y);
                *reinterpret_cast<unsigned*>(C + (size_t)r1 * mCols + c) = *reinterpret_cast<unsigned*>(&h);
            }
        }
    }
}

// ---------------- GRU gates (fp16 inputs) ----------------
__device__ __forceinline__ float sigf(float x) { return 1.f / (1.f + expf(-x)); }

__global__ void k_gate(const float* __restrict__ A, float* __restrict__ out) {
    int gid = blockIdx.x * blockDim.x + threadIdx.x;
    int node = gid >> 5, lane = gid & 31;
    if (node >= N_NODES) return;
    const uint2* gi = reinterpret_cast<const uint2*>(g_gih + (size_t)node * 384);
    const uint2* gh = reinterpret_cast<const uint2*>(g_ghh + (size_t)node * 384);
    float4 gir = h4_to_f4(gi[lane]), giz = h4_to_f4(gi[32 + lane]), gin = h4_to_f4(gi[64 + lane]);
    float4 ghr = h4_to_f4(gh[lane]), ghz = h4_to_f4(gh[32 + lane]), ghn = h4_to_f4(gh[64 + lane]);
    float4 h = reinterpret_cast<const float4*>(A)[node * 32 + lane];
    float4 res;
    { float r = sigf(gir.x + ghr.x), z = sigf(giz.x + ghz.x);
      float n = tanhf(gin.x + r * ghn.x); res.x = (1.f - z) * n + z * h.x; }
    { float r = sigf(gir.y + ghr.y), z = sigf(giz.y + ghz.y);
      float n = tanhf(gin.y + r * ghn.y); res.y = (1.f - z) * n + z * h.y; }
    { float r = sigf(gir.z + ghr.z), z = sigf(giz.z + ghz.z);
      float n = tanhf(gin.z + r * ghn.z); res.z = (1.f - z) * n + z * h.z; }
    { float r = sigf(gir.w + ghr.w), z = sigf(giz.w + ghz.w);
      float n = tanhf(gin.w + r * ghn.w); res.w = (1.f - z) * n + z * h.w; }
    reinterpret_cast<float4*>(out)[node * 32 + lane] = res;
}

// ---------------- launch ----------------
extern "C" void kernel_launch(void* const* d_in, const int* in_sizes, int n_in,
                              void* d_out, int out_size) {
    const float* A    = (const float*)d_in[0];
    const float* W1   = (const float*)d_in[1];
    const float* b1   = (const float*)d_in[2];
    const float* W2   = (const float*)d_in[3];
    const float* b2   = (const float*)d_in[4];
    const float* w_ih = (const float*)d_in[5];
    const float* w_hh = (const float*)d_in[6];
    const float* b_ih = (const float*)d_in[7];
    const float* b_hh = (const float*)d_in[8];
    const void*  ei   = d_in[9];
    float* out = (float*)d_out;

    cudaFuncSetAttribute(k_hmma, cudaFuncAttributeMaxDynamicSharedMemorySize, SM_TOTAL);

    constexpr int RT = (N_NODES + 127) / 128;       // 782 row tiles
    constexpr int NODE_BLKS = (N_NODES + 255) / 256;
    constexpr int EDGE_BLKS = (N_EDGES + 255) / 256;
    constexpr int WARP_BLKS = (N_NODES * 32 + 255) / 256;
    constexpr int CVTW_BLKS = ((128 + 384 + 384) * 32 + 255) / 256;

    k_zero<<<NODE_BLKS, 256>>>((const int*)ei);
    k_logits<<<WARP_BLKS, 256>>>(A, W1);                          // also produces g_ah
    k_cvtW<<<CVTW_BLKS, 256>>>(W2, w_ih, w_hh);
    k_hmma<<<dim3(RT, 4), 256, SM_TOTAL>>>(0, b2, b_ih, b_hh);    // nft + gh (edge-independent)
    k_count<<<EDGE_BLKS, 256>>>(ei);
    k_alloc<<<NODE_BLKS, 256>>>();
    k_fill<<<EDGE_BLKS, 256>>>(ei, b1);
    k_agg<<<WARP_BLKS, 256>>>(A);
    k_hmma<<<dim3(RT, 3), 256, SM_TOTAL>>>(1, b2, b_ih, b_hh);    // gi
    k_gate<<<WARP_BLKS, 256>>>(A, out);
}

// round 15
// speedup vs baseline: 1.0721x; 1.0217x over previous
#include <cuda_runtime.h>
#include <cuda_fp16.h>
#include <math.h>

static constexpr int N_NODES = 100000;
static constexpr int N_EDGES = 1600000;
static constexpr int D = 128;

// ---------------- scratch (device globals; no runtime allocation) ----------------
__device__ __align__(16) __half g_nft[N_NODES * D];       // fp16: A@W2^T + b2
__device__ __align__(16) __half g_gih[N_NODES * 384];     // fp16 gate pre-activations
__device__ __align__(16) __half g_ghh[N_NODES * 384];
__device__ __align__(16) __half g_ah[N_NODES * D];        // A in fp16 (RN)
__device__ __align__(16) __half g_oh[N_NODES * D];        // out_emb in fp16 (RN)
__device__ __align__(16) __half g_w2[128 * D];            // weights fp16
__device__ __align__(16) __half g_wih[384 * D];
__device__ __align__(16) __half g_whh[384 * D];
__device__ float g_logit[N_NODES];
__device__ float g_logit_src[N_NODES];
__device__ int   g_cnt[N_NODES];
__device__ int   g_start[N_NODES];
__device__ int   g_cursor[N_NODES];
__device__ __align__(8) int2 g_pack[N_EDGES];             // {src, bits(exp(score))}
__device__ int   g_counter;
__device__ int   g_is64;

// ---------------- fp16 helpers ----------------
__device__ __forceinline__ void cvt4_h(float4 v, __half* dst, long long i4) {
    __half2 p0 = __floats2half2_rn(v.x, v.y);
    __half2 p1 = __floats2half2_rn(v.z, v.w);
    uint2 u;
    u.x = *reinterpret_cast<unsigned*>(&p0);
    u.y = *reinterpret_cast<unsigned*>(&p1);
    reinterpret_cast<uint2*>(dst)[i4] = u;
}
__device__ __forceinline__ float4 h4_to_f4(uint2 u) {
    __half2 a = *reinterpret_cast<__half2*>(&u.x);
    __half2 b = *reinterpret_cast<__half2*>(&u.y);
    float2 fa = __half22float2(a), fb = __half22float2(b);
    return make_float4(fa.x, fa.y, fb.x, fb.y);
}

// dtype-adaptive edge index load, clamped to [0, N_NODES).
__device__ __forceinline__ int load_idx(const void* ei, long long i, int is64) {
    long long v = is64 ? reinterpret_cast<const long long*>(ei)[i]
                       : (long long)reinterpret_cast<const int*>(ei)[i];
    v = v < 0 ? 0 : (v >= N_NODES ? N_NODES - 1 : v);
    return (int)v;
}

// ---------------- merged prep: zero counters + logits + A->fp16 + W->fp16 ----------------
// segment 0: [0, N_NODES*32)             : warp-per-node logits + A conversion
// segment 1: [S1, S1 + 896*32)           : weight conversion (128+384+384 rows)
// segment 2: [S2, S2 + NODE_BLK_IDS)     : zero g_cnt (+ g_counter, g_is64)
static constexpr long long PREP_S1 = (long long)N_NODES * 32;
static constexpr long long PREP_S2 = PREP_S1 + 896 * 32;
static constexpr long long PREP_TOTAL = PREP_S2 + N_NODES;

__global__ void k_prep(const float* __restrict__ A, const float* __restrict__ W1,
                       const float* __restrict__ W2, const float* __restrict__ wih,
                       const float* __restrict__ whh, const int* __restrict__ eiw) {
    long long gid = (long long)blockIdx.x * blockDim.x + threadIdx.x;
    if (gid < PREP_S1) {
        int node = (int)(gid >> 5), lane = (int)(gid & 31);
        float4 x  = reinterpret_cast<const float4*>(A)[node * 32 + lane];
        cvt4_h(x, g_ah, gid);
        float4 wd = __ldg(reinterpret_cast<const float4*>(W1) + lane);
        float4 ws = __ldg(reinterpret_cast<const float4*>(W1) + 32 + lane);
        float d = x.x * wd.x + x.y * wd.y + x.z * wd.z + x.w * wd.w;
        float s = x.x * ws.x + x.y * ws.y + x.z * ws.z + x.w * ws.w;
#pragma unroll
        for (int o = 16; o; o >>= 1) {
            d += __shfl_xor_sync(0xffffffffu, d, o);
            s += __shfl_xor_sync(0xffffffffu, s, o);
        }
        if (lane == 0) { g_logit[node] = d; g_logit_src[node] = s; }
    } else if (gid < PREP_S2) {
        int i = (int)(gid - PREP_S1);
        const int n2 = 128 * 32, nih = 384 * 32;
        if (i < n2)
            cvt4_h(reinterpret_cast<const float4*>(W2)[i], g_w2, i);
        else if (i < n2 + nih)
            cvt4_h(reinterpret_cast<const float4*>(wih)[i - n2], g_wih, i - n2);
        else
            cvt4_h(reinterpret_cast<const float4*>(whh)[i - n2 - nih], g_whh, i - n2 - nih);
    } else if (gid < PREP_TOTAL) {
        int i = (int)(gid - PREP_S2);
        g_cnt[i] = 0;
        if (i == 0) {
            g_counter = 0;
            g_is64 = (eiw[1] == 0 && eiw[3] == 0 && eiw[5] == 0 && eiw[7] == 0) ? 1 : 0;
        }
    }
}

__global__ void k_count(const void* __restrict__ ei) {
    int e = blockIdx.x * blockDim.x + threadIdx.x;
    if (e >= N_EDGES) return;
    atomicAdd(&g_cnt[load_idx(ei, (long long)N_EDGES + e, g_is64)], 1);
}

__global__ void k_alloc() {
    int n = blockIdx.x * blockDim.x + threadIdx.x;
    if (n >= N_NODES) return;
    int c = g_cnt[n];
    int s = atomicAdd(&g_counter, c);
    g_start[n] = s;
    g_cursor[n] = s;
}

// segment_max elided: cancels exactly in attn = e/denom; scores are O(1).
__global__ void k_fill(const void* __restrict__ ei, const float* __restrict__ b1) {
    int e = blockIdx.x * blockDim.x + threadIdx.x;
    if (e >= N_EDGES) return;
    int is64 = g_is64;
    int src = load_idx(ei, e, is64);
    int dst = load_idx(ei, (long long)N_EDGES + e, is64);
    float sc = g_logit[dst] + g_logit_src[src] + __ldg(b1);
    sc = sc > 0.f ? sc : 0.2f * sc;
    float es = expf(sc);
    int pos = atomicAdd(&g_cursor[dst], 1);
    if (pos < N_EDGES) g_pack[pos] = make_int2(src, __float_as_int(es));
}

// warp per node, single pass: Sum(w*v) and Sum(w) together; unroll 4 for MLP.
__global__ void k_agg(const float* __restrict__ A) {
    int gid = blockIdx.x * blockDim.x + threadIdx.x;
    int node = gid >> 5, lane = gid & 31;
    if (node >= N_NODES) return;
    int s0 = g_start[node];
    int len = g_cnt[node];
    if (s0 + len > N_EDGES) len = N_EDGES - s0 > 0 ? N_EDGES - s0 : 0;

    float4 out;
    if (len > 0) {
        float dsum = 0.f;
        float ax = 0.f, ay = 0.f, az = 0.f, aw = 0.f;
        const uint2* nf = reinterpret_cast<const uint2*>(g_nft);
#pragma unroll 4
        for (int t = 0; t < len; ++t) {
            int2 p = g_pack[s0 + t];
            float w = __int_as_float(p.y);
            dsum += w;
            float4 v = h4_to_f4(nf[(size_t)p.x * 32 + lane]);
            ax = fmaf(w, v.x, ax); ay = fmaf(w, v.y, ay);
            az = fmaf(w, v.z, az); aw = fmaf(w, v.w, aw);
        }
        float inv = 1.f / dsum;
        ax *= inv; ay *= inv; az *= inv; aw *= inv;
        out.x = ax > 0.f ? ax : (expf(ax) - 1.f);
        out.y = ay > 0.f ? ay : (expf(ay) - 1.f);
        out.z = az > 0.f ? az : (expf(az) - 1.f);
        out.w = aw > 0.f ? aw : (expf(aw) - 1.f);
    } else {
        out = reinterpret_cast<const float4*>(A)[node * 32 + lane];
    }
    cvt4_h(out, g_oh, (long long)node * 32 + lane);
}

// ---------------- HMMA GEMM (fp16 mma.sync, 128x128 tile, 2 CTAs/SM, pipelined) ----
// At the legacy-HMMA rate ceiling (~194 TF/s measured across schedules); kept as-is.

static constexpr int SM_X = 0;
static constexpr int SM_W = 32768;
static constexpr int SM_TOTAL = 65536;

__device__ __forceinline__ unsigned smem_u32(const void* p) {
    unsigned a;
    asm("{ .reg .u64 t; cvta.to.shared.u64 t, %1; cvt.u32.u64 %0, t; }" : "=r"(a) : "l"(p));
    return a;
}
__device__ __forceinline__ void cpasync16(unsigned dst, const void* src, bool valid) {
    int sz = valid ? 16 : 0;
    asm volatile("cp.async.cg.shared.global [%0], [%1], 16, %2;"
                 :: "r"(dst), "l"(src), "r"(sz) : "memory");
}
__device__ __forceinline__ void ldsm4(unsigned& r0, unsigned& r1, unsigned& r2, unsigned& r3, unsigned a) {
    asm volatile("ldmatrix.sync.aligned.m8n8.x4.shared.b16 {%0,%1,%2,%3}, [%4];"
                 : "=r"(r0), "=r"(r1), "=r"(r2), "=r"(r3) : "r"(a));
}
__device__ __forceinline__ void mma16816(float* c, unsigned a0, unsigned a1, unsigned a2, unsigned a3,
                                         unsigned b0, unsigned b1) {
    asm volatile("mma.sync.aligned.m16n8k16.row.col.f32.f16.f16.f32 "
                 "{%0,%1,%2,%3}, {%4,%5,%6,%7}, {%8,%9}, {%0,%1,%2,%3};"
                 : "+f"(c[0]), "+f"(c[1]), "+f"(c[2]), "+f"(c[3])
                 : "r"(a0), "r"(a1), "r"(a2), "r"(a3), "r"(b0), "r"(b1));
}

__global__ __launch_bounds__(256, 2) void k_hmma(
    int mode,                     // 0 = nft+gh (grid RT x 4), 1 = gi (grid RT x 3)
    const float* __restrict__ b2,
    const float* __restrict__ bih,
    const float* __restrict__ bhh)
{
    extern __shared__ __align__(128) char smem[];
    const int tid = threadIdx.x, wid = tid >> 5, lane = tid & 31;
    const unsigned sb = smem_u32(smem);
    const int rowBase = blockIdx.x * 128;

    const __half *Xp, *Wp;
    const float* bias;
    __half* C;
    int mCols, colBase;
    if (mode == 0) {
        int y = blockIdx.y;
        if (y == 0) { Xp = g_ah; Wp = g_w2;  bias = b2;  C = g_nft; mCols = 128; colBase = 0; }
        else        { Xp = g_ah; Wp = g_whh; bias = bhh; C = g_ghh; mCols = 384; colBase = (y - 1) * 128; }
    } else {
        Xp = g_oh; Wp = g_wih; bias = bih; C = g_gih; mCols = 384; colBase = blockIdx.y * 128;
    }
    const __half* Wcol = Wp + (size_t)colBase * 128;

#pragma unroll
    for (int it = 0; it < 8; ++it) {
        int lc  = it * 256 + tid;        // 0..2047
        int row = lc >> 4;
        int ch  = lc & 15;
        unsigned so = (unsigned)(row * 256 + ((ch ^ (row & 7)) << 4));
        int gr = rowBase + row;
        cpasync16(sb + SM_X + so, Xp + (size_t)gr * 128 + ch * 8, gr < N_NODES);
        cpasync16(sb + SM_W + so, Wcol + (size_t)row * 128 + ch * 8, true);
    }
    asm volatile("cp.async.commit_group;" ::: "memory");

    const int warpRow = (wid >> 2) * 64;   // 0 or 64
    const int warpCol = (wid & 3) * 32;    // 0,32,64,96
    const int arow = warpRow + (lane & 15);
    const int ahalf = lane >> 4;
    const int bn = warpCol + ((lane >> 4) << 3) + (lane & 7);
    const int bhalf = (lane >> 3) & 1;

    float acc[4][4][4];
#pragma unroll
    for (int mi = 0; mi < 4; ++mi)
#pragma unroll
        for (int nj = 0; nj < 4; ++nj)
#pragma unroll
            for (int q = 0; q < 4; ++q) acc[mi][nj][q] = 0.f;

    asm volatile("cp.async.wait_group 0;" ::: "memory");
    __syncthreads();

    const unsigned ab = sb + SM_X;
    const unsigned bb = sb + SM_W;

    unsigned a[2][4][4], b[2][2][4];
#pragma unroll
    for (int mi = 0; mi < 4; ++mi) {
        int r = arow + mi * 16;
        unsigned ch = (unsigned)(ahalf ^ (r & 7));
        ldsm4(a[0][mi][0], a[0][mi][1], a[0][mi][2], a[0][mi][3], ab + r * 256 + (ch << 4));
    }
#pragma unroll
    for (int q = 0; q < 2; ++q) {
        int n = bn + q * 16;
        unsigned ch = (unsigned)(bhalf ^ (n & 7));
        ldsm4(b[0][q][0], b[0][q][1], b[0][q][2], b[0][q][3], bb + n * 256 + (ch << 4));
    }

#pragma unroll
    for (int s = 0; s < 8; ++s) {
        const int cur = s & 1, nxt = cur ^ 1;
        if (s < 7) {
#pragma unroll
            for (int mi = 0; mi < 4; ++mi) {
                int r = arow + mi * 16;
                unsigned ch = (unsigned)((2 * (s + 1) + ahalf) ^ (r & 7));
                ldsm4(a[nxt][mi][0], a[nxt][mi][1], a[nxt][mi][2], a[nxt][mi][3],
                      ab + r * 256 + (ch << 4));
            }
#pragma unroll
            for (int q = 0; q < 2; ++q) {
                int n = bn + q * 16;
                unsigned ch = (unsigned)((2 * (s + 1) + bhalf) ^ (n & 7));
                ldsm4(b[nxt][q][0], b[nxt][q][1], b[nxt][q][2], b[nxt][q][3],
                      bb + n * 256 + (ch << 4));
            }
        }
#pragma unroll
        for (int mi = 0; mi < 4; ++mi) {
#pragma unroll
            for (int nj = 0; nj < 4; ++nj) {
                unsigned b0 = b[cur][nj >> 1][(nj & 1) * 2];
                unsigned b1 = b[cur][nj >> 1][(nj & 1) * 2 + 1];
                mma16816(acc[mi][nj], a[cur][mi][0], a[cur][mi][1], a[cur][mi][2], a[cur][mi][3], b0, b1);
            }
        }
    }

    const int colOff = colBase + warpCol + 2 * (lane & 3);
#pragma unroll
    for (int nj = 0; nj < 4; ++nj) {
        int c = colOff + nj * 8;
        float2 b2v = __ldg(reinterpret_cast<const float2*>(bias + c));
#pragma unroll
        for (int mi = 0; mi < 4; ++mi) {
            int r0 = rowBase + warpRow + mi * 16 + (lane >> 2);
            if (r0 < N_NODES) {
                __half2 h = __floats2half2_rn(acc[mi][nj][0] + b2v.x, acc[mi][nj][1] + b2v.y);
                *reinterpret_cast<unsigned*>(C + (size_t)r0 * mCols + c) = *reinterpret_cast<unsigned*>(&h);
            }
            int r1 = r0 + 8;
            if (r1 < N_NODES) {
                __half2 h = __floats2half2_rn(acc[mi][nj][2] + b2v.x, acc[mi][nj][3] + b2v.y);
                *reinterpret_cast<unsigned*>(C + (size_t)r1 * mCols + c) = *reinterpret_cast<unsigned*>(&h);
            }
        }
    }
}

// ---------------- GRU gates (all-fp16 inputs incl. residual h) ----------------
__device__ __forceinline__ float sigf(float x) { return 1.f / (1.f + expf(-x)); }

__global__ void k_gate(float* __restrict__ out) {
    int gid = blockIdx.x * blockDim.x + threadIdx.x;
    int node = gid >> 5, lane = gid & 31;
    if (node >= N_NODES) return;
    const uint2* gi = reinterpret_cast<const uint2*>(g_gih + (size_t)node * 384);
    const uint2* gh = reinterpret_cast<const uint2*>(g_ghh + (size_t)node * 384);
    float4 gir = h4_to_f4(gi[lane]), giz = h4_to_f4(gi[32 + lane]), gin = h4_to_f4(gi[64 + lane]);
    float4 ghr = h4_to_f4(gh[lane]), ghz = h4_to_f4(gh[32 + lane]), ghn = h4_to_f4(gh[64 + lane]);
    float4 h = h4_to_f4(reinterpret_cast<const uint2*>(g_ah)[node * 32 + lane]);
    float4 res;
    { float r = sigf(gir.x + ghr.x), z = sigf(giz.x + ghz.x);
      float n = tanhf(gin.x + r * ghn.x); res.x = (1.f - z) * n + z * h.x; }
    { float r = sigf(gir.y + ghr.y), z = sigf(giz.y + ghz.y);
      float n = tanhf(gin.y + r * ghn.y); res.y = (1.f - z) * n + z * h.y; }
    { float r = sigf(gir.z + ghr.z), z = sigf(giz.z + ghz.z);
      float n = tanhf(gin.z + r * ghn.z); res.z = (1.f - z) * n + z * h.z; }
    { float r = sigf(gir.w + ghr.w), z = sigf(giz.w + ghz.w);
      float n = tanhf(gin.w + r * ghn.w); res.w = (1.f - z) * n + z * h.w; }
    reinterpret_cast<float4*>(out)[node * 32 + lane] = res;
}

// ---------------- launch ----------------
extern "C" void kernel_launch(void* const* d_in, const int* in_sizes, int n_in,
                              void* d_out, int out_size) {
    const float* A    = (const float*)d_in[0];
    const float* W1   = (const float*)d_in[1];
    const float* b1   = (const float*)d_in[2];
    const float* W2   = (const float*)d_in[3];
    const float* b2   = (const float*)d_in[4];
    const float* w_ih = (const float*)d_in[5];
    const float* w_hh = (const float*)d_in[6];
    const float* b_ih = (const float*)d_in[7];
    const float* b_hh = (const float*)d_in[8];
    const void*  ei   = d_in[9];
    float* out = (float*)d_out;

    cudaFuncSetAttribute(k_hmma, cudaFuncAttributeMaxDynamicSharedMemorySize, SM_TOTAL);

    constexpr int RT = (N_NODES + 127) / 128;       // 782 row tiles
    constexpr int NODE_BLKS = (N_NODES + 255) / 256;
    constexpr int EDGE_BLKS = (N_EDGES + 255) / 256;
    constexpr int WARP_BLKS = (N_NODES * 32 + 255) / 256;
    constexpr int PREP_BLKS = (int)((PREP_TOTAL + 255) / 256);

    k_prep<<<PREP_BLKS, 256>>>(A, W1, W2, w_ih, w_hh, (const int*)ei);
    k_hmma<<<dim3(RT, 4), 256, SM_TOTAL>>>(0, b2, b_ih, b_hh);    // nft + gh (edge-independent)
    k_count<<<EDGE_BLKS, 256>>>(ei);
    k_alloc<<<NODE_BLKS, 256>>>();
    k_fill<<<EDGE_BLKS, 256>>>(ei, b1);
    k_agg<<<WARP_BLKS, 256>>>(A);
    k_hmma<<<dim3(RT, 3), 256, SM_TOTAL>>>(1, b2, b_ih, b_hh);    // gi
    k_gate<<<WARP_BLKS, 256>>>(out);
}